// round 1
// baseline (speedup 1.0000x reference)
#include <cuda_runtime.h>

#define NQ 10
#define NL 4
#define NC 4
#define BATCH 2048

// Precomputed Rot matrices: [NL][NQ][8] = (m00r,m00i,m01r,m01i,m10r,m10i,m11r,m11i)
__device__ float g_rot[NL * NQ * 8];

__global__ void rot_precompute_kernel(const float* __restrict__ w) {
    int i = threadIdx.x;
    if (i < NL * NQ) {
        float phi = w[i * 3 + 0], theta = w[i * 3 + 1], omega = w[i * 3 + 2];
        float st, ct;  sincosf(0.5f * theta, &st, &ct);
        float spo, cpo; sincosf(0.5f * (phi + omega), &spo, &cpo);
        float spm, cpm; sincosf(0.5f * (phi - omega), &spm, &cpm);
        float* m = g_rot + i * 8;
        // m00 = e^{-i(phi+omega)/2} cos(theta/2)
        m[0] =  cpo * ct;  m[1] = -spo * ct;
        // m01 = -e^{+i(phi-omega)/2} sin(theta/2)
        m[2] = -cpm * st;  m[3] = -spm * st;
        // m10 = e^{-i(phi-omega)/2} sin(theta/2)
        m[4] =  cpm * st;  m[5] = -spm * st;
        // m11 = e^{+i(phi+omega)/2} cos(theta/2)
        m[6] =  cpo * ct;  m[7] =  spo * ct;
    }
}

// Fused gate M = Rot * RX, RX = [[c, -i s], [-i s, c]]
__device__ __forceinline__ void build_fused(const float* __restrict__ rm,
                                            float c, float s, float* M) {
    float R00r = rm[0], R00i = rm[1], R01r = rm[2], R01i = rm[3];
    float R10r = rm[4], R10i = rm[5], R11r = rm[6], R11i = rm[7];
    M[0] =  c * R00r + s * R01i;   M[1] =  c * R00i - s * R01r;
    M[2] =  s * R00i + c * R01r;   M[3] = -s * R00r + c * R01i;
    M[4] =  c * R10r + s * R11i;   M[5] =  c * R10i - s * R11r;
    M[6] =  s * R10i + c * R11r;   M[7] = -s * R10r + c * R11i;
}

// 1q gate on a LOCAL bit (compile-time MASK in 1..16): pure register math.
template <int MASK>
__device__ __forceinline__ void apply_local(float* ar, float* ai, const float* M) {
#pragma unroll
    for (int j = 0; j < 32; j++) {
        if ((j & MASK) == 0) {
            const int k = j | MASK;
            float a0r = ar[j], a0i = ai[j], a1r = ar[k], a1i = ai[k];
            ar[j] = M[0] * a0r - M[1] * a0i + M[2] * a1r - M[3] * a1i;
            ai[j] = M[0] * a0i + M[1] * a0r + M[2] * a1i + M[3] * a1r;
            ar[k] = M[4] * a0r - M[5] * a0i + M[6] * a1r - M[7] * a1i;
            ai[k] = M[4] * a0i + M[5] * a0r + M[6] * a1i + M[7] * a1r;
        }
    }
}

// 1q gate on a LANE bit (compile-time LM in 1..16): shfl_xor exchange.
template <int LM>
__device__ __forceinline__ void apply_lane(float* ar, float* ai, int lane, const float* M) {
    bool r = (lane & LM) != 0;
    float car = r ? M[6] : M[0];   // coeff for own amplitude
    float cai = r ? M[7] : M[1];
    float cbr = r ? M[4] : M[2];   // coeff for partner amplitude
    float cbi = r ? M[5] : M[3];
#pragma unroll
    for (int j = 0; j < 32; j++) {
        float otr = __shfl_xor_sync(0xffffffffu, ar[j], LM);
        float oti = __shfl_xor_sync(0xffffffffu, ai[j], LM);
        float sr = ar[j], si = ai[j];
        ar[j] = car * sr - cai * si + cbr * otr - cbi * oti;
        ai[j] = car * si + cai * sr + cbr * oti + cbi * otr;
    }
}

// CNOT: control lane bit CM, target lane bit TM
template <int CM, int TM>
__device__ __forceinline__ void cnot_lane_lane(float* ar, float* ai, int lane) {
    bool c = (lane & CM) != 0;
#pragma unroll
    for (int j = 0; j < 32; j++) {
        float otr = __shfl_xor_sync(0xffffffffu, ar[j], TM);
        float oti = __shfl_xor_sync(0xffffffffu, ai[j], TM);
        if (c) { ar[j] = otr; ai[j] = oti; }
    }
}

// CNOT: control = lane bit 0 (wire 4), target = local bit 16 (wire 5)
__device__ __forceinline__ void cnot_lane_local(float* ar, float* ai, int lane) {
    if (lane & 1) {
#pragma unroll
        for (int j = 0; j < 16; j++) {
            float t;
            t = ar[j]; ar[j] = ar[j + 16]; ar[j + 16] = t;
            t = ai[j]; ai[j] = ai[j + 16]; ai[j + 16] = t;
        }
    }
}

// CNOT: control local bit CM, target local bit TM — pure register permutation.
template <int CM, int TM>
__device__ __forceinline__ void cnot_local_local(float* ar, float* ai) {
#pragma unroll
    for (int j = 0; j < 32; j++) {
        if ((j & CM) != 0 && (j & TM) == 0) {
            const int k = j | TM;
            float t;
            t = ar[j]; ar[j] = ar[k]; ar[k] = t;
            t = ai[j]; ai[j] = ai[k]; ai[k] = t;
        }
    }
}

// CNOT: control = local bit 0 (wire 9), target = lane bit 16 (wire 0)
__device__ __forceinline__ void cnot_local_lane(float* ar, float* ai) {
#pragma unroll
    for (int j = 1; j < 32; j += 2) {
        ar[j] = __shfl_xor_sync(0xffffffffu, ar[j], 16);
        ai[j] = __shfl_xor_sync(0xffffffffu, ai[j], 16);
    }
}

__device__ __forceinline__ float signed_warp_sum(float p, int lane, int mask) {
    float v = (lane & mask) ? -p : p;
    v += __shfl_xor_sync(0xffffffffu, v, 16);
    v += __shfl_xor_sync(0xffffffffu, v, 8);
    v += __shfl_xor_sync(0xffffffffu, v, 4);
    v += __shfl_xor_sync(0xffffffffu, v, 2);
    v += __shfl_xor_sync(0xffffffffu, v, 1);
    return v;
}

__global__ void __launch_bounds__(256)
vqc_kernel(const float* __restrict__ x,
           const float* __restrict__ bias,
           const float* __restrict__ scale,
           float* __restrict__ out) {
    __shared__ float srot[NL * NQ * 8];
    // Stage rot matrices into shared memory (broadcast reads later).
    for (int i = threadIdx.x; i < NL * NQ * 8; i += blockDim.x)
        srot[i] = g_rot[i];
    __syncthreads();

    const int lane = threadIdx.x & 31;
    const int b = (blockIdx.x * blockDim.x + threadIdx.x) >> 5;  // batch element

    // Per-wire half-angle cos/sin held on lanes 0..9, broadcast via shfl.
    float xc = 0.0f, xs = 0.0f;
    if (lane < NQ) {
        float h = 0.5f * x[b * NQ + lane];
        sincosf(h, &xs, &xc);
    }

    // State: 1024 amplitudes. lane = bits [9:5], local j = bits [4:0].
    // wire q -> global bit (9-q): wires 0..4 = lane bits 16,8,4,2,1;
    //                             wires 5..9 = local bits 16,8,4,2,1.
    float ar[32], ai[32];
#pragma unroll
    for (int j = 0; j < 32; j++) { ar[j] = 0.0f; ai[j] = 0.0f; }
    if (lane == 0) ar[0] = 1.0f;  // |0...0>

    float M[8];
#pragma unroll 1
    for (int l = 0; l < NL; l++) {
        const float* rl = srot + l * NQ * 8;
        // Fused (Rot*RX) gates, wires 0..9
        build_fused(rl + 0,  __shfl_sync(0xffffffffu, xc, 0), __shfl_sync(0xffffffffu, xs, 0), M);
        apply_lane<16>(ar, ai, lane, M);
        build_fused(rl + 8,  __shfl_sync(0xffffffffu, xc, 1), __shfl_sync(0xffffffffu, xs, 1), M);
        apply_lane<8>(ar, ai, lane, M);
        build_fused(rl + 16, __shfl_sync(0xffffffffu, xc, 2), __shfl_sync(0xffffffffu, xs, 2), M);
        apply_lane<4>(ar, ai, lane, M);
        build_fused(rl + 24, __shfl_sync(0xffffffffu, xc, 3), __shfl_sync(0xffffffffu, xs, 3), M);
        apply_lane<2>(ar, ai, lane, M);
        build_fused(rl + 32, __shfl_sync(0xffffffffu, xc, 4), __shfl_sync(0xffffffffu, xs, 4), M);
        apply_lane<1>(ar, ai, lane, M);
        build_fused(rl + 40, __shfl_sync(0xffffffffu, xc, 5), __shfl_sync(0xffffffffu, xs, 5), M);
        apply_local<16>(ar, ai, M);
        build_fused(rl + 48, __shfl_sync(0xffffffffu, xc, 6), __shfl_sync(0xffffffffu, xs, 6), M);
        apply_local<8>(ar, ai, M);
        build_fused(rl + 56, __shfl_sync(0xffffffffu, xc, 7), __shfl_sync(0xffffffffu, xs, 7), M);
        apply_local<4>(ar, ai, M);
        build_fused(rl + 64, __shfl_sync(0xffffffffu, xc, 8), __shfl_sync(0xffffffffu, xs, 8), M);
        apply_local<2>(ar, ai, M);
        build_fused(rl + 72, __shfl_sync(0xffffffffu, xc, 9), __shfl_sync(0xffffffffu, xs, 9), M);
        apply_local<1>(ar, ai, M);

        // CNOT ring q -> (q+1)%10, in order q = 0..9
        cnot_lane_lane<16, 8>(ar, ai, lane);   // q=0
        cnot_lane_lane<8, 4>(ar, ai, lane);    // q=1
        cnot_lane_lane<4, 2>(ar, ai, lane);    // q=2
        cnot_lane_lane<2, 1>(ar, ai, lane);    // q=3
        cnot_lane_local(ar, ai, lane);         // q=4
        cnot_local_local<16, 8>(ar, ai);       // q=5
        cnot_local_local<8, 4>(ar, ai);        // q=6
        cnot_local_local<4, 2>(ar, ai);        // q=7
        cnot_local_local<2, 1>(ar, ai);        // q=8
        cnot_local_lane(ar, ai);               // q=9
    }

    // Probabilities; per-lane partial sum.
    float p = 0.0f;
#pragma unroll
    for (int j = 0; j < 32; j++)
        p += ar[j] * ar[j] + ai[j] * ai[j];

    // <Z> on wires 0..3 = lane bits 16,8,4,2
    float ev0 = signed_warp_sum(p, lane, 16);
    float ev1 = signed_warp_sum(p, lane, 8);
    float ev2 = signed_warp_sum(p, lane, 4);
    float ev3 = signed_warp_sum(p, lane, 2);

    if (lane == 0) {
        float t0 = (ev0 + bias[0]) * scale[0];
        float t1 = (ev1 + bias[1]) * scale[1];
        float t2 = (ev2 + bias[2]) * scale[2];
        float t3 = (ev3 + bias[3]) * scale[3];
        float m = fmaxf(fmaxf(t0, t1), fmaxf(t2, t3));
        float e0 = expf(t0 - m), e1 = expf(t1 - m), e2 = expf(t2 - m), e3 = expf(t3 - m);
        float inv = 1.0f / (e0 + e1 + e2 + e3);
        float4 o = make_float4(e0 * inv, e1 * inv, e2 * inv, e3 * inv);
        reinterpret_cast<float4*>(out)[b] = o;
    }
}

extern "C" void kernel_launch(void* const* d_in, const int* in_sizes, int n_in,
                              void* d_out, int out_size) {
    const float* x       = (const float*)d_in[0];  // (B, NQ)
    const float* weights = (const float*)d_in[1];  // (NL, NQ, 3)
    const float* bias    = (const float*)d_in[2];  // (C,)
    const float* scale   = (const float*)d_in[3];  // (C,)
    float* out = (float*)d_out;                    // (B, C)

    rot_precompute_kernel<<<1, 64>>>(weights);
    // 8 warps per block -> 8 batch elements per block
    vqc_kernel<<<BATCH / 8, 256>>>(x, bias, scale, out);
}

// round 3
// speedup vs baseline: 1.3894x; 1.3894x over previous
#include <cuda_runtime.h>

#define NQ 10
#define NL 4
#define NC 4
#define BATCH 2048

typedef unsigned long long u64;

// ============================================================================
// GF(2) linear-map tracking of the CNOT ring (all compile-time).
// Index bits: wire q <-> bit (9-q). Bits 5..9 = lane bits 0..4, bits 0..4 = local.
// Ring permutation T = M0 M1 ... M9 (function composition, q=0 applied first).
// Invariant: psi_phys[p] = sigma[F p], F = T^l at layer l.
// Gate on physical bit b: stored pair-XOR mask = column b of F,
//                         role(s) = <row_b(F^{-1}), s>.
// Measurement sign mask for bit b: row b of T^{-NL}.
// ============================================================================

struct G10 { unsigned r[10]; };

__host__ __device__ constexpr G10 gid10() {
    G10 c{};
    for (int i = 0; i < 10; i++) c.r[i] = 1u << i;
    return c;
}
__host__ __device__ constexpr G10 gmul(const G10 a, const G10 b) {
    G10 c{};
    for (int i = 0; i < 10; i++) {
        unsigned m = 0;
        for (int j = 0; j < 10; j++)
            if ((a.r[i] >> j) & 1u) m ^= b.r[j];
        c.r[i] = m;
    }
    return c;
}
// T: row_i = e_i + e_{i+1} (i<8), row_8 = e0+e8+e9, row_9 = e0+e9
__host__ __device__ constexpr G10 makeT() {
    G10 c{};
    for (int i = 0; i < 8; i++) c.r[i] = (1u << i) | (1u << (i + 1));
    c.r[8] = 0x301u;
    c.r[9] = 0x201u;
    return c;
}
// T^{-1}: row_i = bits i..9 (i<9), row_9 = bits 0..8
__host__ __device__ constexpr G10 makeTinv() {
    G10 c{};
    for (int i = 0; i < 9; i++) c.r[i] = (0x3FFu >> i) << i;
    c.r[9] = 0x1FFu;
    return c;
}
__host__ __device__ constexpr G10 gpow(const G10 a, int k) {
    G10 c = gid10();
    for (int t = 0; t < k; t++) c = gmul(a, c);
    return c;
}
__host__ __device__ constexpr bool iseq(const G10 a, const G10 b) {
    for (int i = 0; i < 10; i++) if (a.r[i] != b.r[i]) return false;
    return true;
}
static_assert(iseq(gmul(makeT(), makeTinv()), gid10()), "Tinv wrong");

__host__ __device__ constexpr unsigned colmask(const G10 m, int b) {
    unsigned v = 0;
    for (int i = 0; i < 10; i++) v |= ((m.r[i] >> b) & 1u) << i;
    return v;
}
__host__ __device__ constexpr unsigned gate_mask(int l, int q) {
    return colmask(gpow(makeT(), l), 9 - q);      // column b of T^l
}
__host__ __device__ constexpr unsigned gate_role(int l, int q) {
    return gpow(makeTinv(), l).r[9 - q];          // row b of T^{-l}
}
__host__ __device__ constexpr unsigned meas_row(int wire) {
    return gpow(makeTinv(), NL).r[9 - wire];      // row b of T^{-NL}
}
__host__ __device__ constexpr int par10(unsigned v) {
    int p = 0;
    for (int i = 0; i < 10; i++) p ^= (int)((v >> i) & 1u);
    return p;
}

// ============================================================================
// Packed f32x2 helpers (Blackwell FFMA2)
// ============================================================================
__device__ __forceinline__ u64 pk(float lo, float hi) {
    u64 d;
    asm("mov.b64 %0, {%1, %2};" : "=l"(d) : "f"(lo), "f"(hi));
    return d;
}
__device__ __forceinline__ void upk(u64 v, float& lo, float& hi) {
    asm("mov.b64 {%0, %1}, %2;" : "=f"(lo), "=f"(hi) : "l"(v));
}
__device__ __forceinline__ u64 f2fma(u64 a, u64 b, u64 c) {
    u64 d;
    asm("fma.rn.f32x2 %0, %1, %2, %3;" : "=l"(d) : "l"(a), "l"(b), "l"(c));
    return d;
}
__device__ __forceinline__ u64 f2mul(u64 a, u64 b) {
    u64 d;
    asm("mul.rn.f32x2 %0, %1, %2;" : "=l"(d) : "l"(a), "l"(b));
    return d;
}
__device__ __forceinline__ u64 swap2(u64 v) { return (v >> 32) | (v << 32); }
__device__ __forceinline__ u64 shfl64(u64 v, int m) {
    return __shfl_xor_sync(0xffffffffu, v, m);
}

// ============================================================================
// Rot matrix precompute: [NL][NQ][8] = (m00r,m00i,m01r,m01i,m10r,m10i,m11r,m11i)
// ============================================================================
__device__ float g_rot[NL * NQ * 8];

__global__ void rot_precompute_kernel(const float* __restrict__ w) {
    int i = threadIdx.x;
    if (i < NL * NQ) {
        float phi = w[i * 3 + 0], theta = w[i * 3 + 1], omega = w[i * 3 + 2];
        float st, ct;  sincosf(0.5f * theta, &st, &ct);
        float spo, cpo; sincosf(0.5f * (phi + omega), &spo, &cpo);
        float spm, cpm; sincosf(0.5f * (phi - omega), &spm, &cpm);
        float* m = g_rot + i * 8;
        m[0] =  cpo * ct;  m[1] = -spo * ct;
        m[2] = -cpm * st;  m[3] = -spm * st;
        m[4] =  cpm * st;  m[5] = -spm * st;
        m[6] =  cpo * ct;  m[7] =  spo * ct;
    }
}

// Fused gate M = Rot * RX;  RX = [[c, -i s], [-i s, c]]
__device__ __forceinline__ void build_fused(const float* __restrict__ rm,
                                            float c, float s, float* M) {
    float R00r = rm[0], R00i = rm[1], R01r = rm[2], R01i = rm[3];
    float R10r = rm[4], R10i = rm[5], R11r = rm[6], R11i = rm[7];
    M[0] =  c * R00r + s * R01i;   M[1] =  c * R00i - s * R01r;
    M[2] =  s * R00i + c * R01r;   M[3] = -s * R00r + c * R01i;
    M[4] =  c * R10r + s * R11i;   M[5] =  c * R10i - s * R11r;
    M[6] =  s * R10i + c * R11r;   M[7] = -s * R10r + c * R11i;
}

// ============================================================================
// Generalized 1q gate: pair-XOR mask (LM lane part, JM local part), role-parity
// mask (RL lane, RJ local). State packed: group g holds j=2g (lo), 2g+1 (hi).
// role0: out = m00*self + m01*partner ; role1: out = m11*self + m10*partner
// role = par(lane&RL) ^ par(j&RJ)
// ============================================================================
template <int LM, int JM, int RL, int RJ>
__device__ __forceinline__ void gate_apply(u64* Vr, u64* Vi, int lane,
                                           const float* M) {
    constexpr int JH = JM >> 1, JL = JM & 1;
    constexpr int JHB = JH & (-JH);   // canonical (lowest) bit for orbit pick
    constexpr int RJH = RJ >> 1, RJL = RJ & 1;

    const bool rl = (RL != 0) && ((__popc(lane & RL) & 1) != 0);
    const float s0Ar = rl ? M[6] : M[0], s0Ai = rl ? M[7] : M[1];
    const float s0Br = rl ? M[4] : M[2], s0Bi = rl ? M[5] : M[3];
    const float s1Ar = rl ? M[0] : M[6], s1Ai = rl ? M[1] : M[7];
    const float s1Br = rl ? M[2] : M[4], s1Bi = rl ? M[3] : M[5];

    // pack variant v: lo = set(v), hi = set(v ^ RJL)
    const u64 PAr0  = pk(s0Ar, RJL ? s1Ar : s0Ar);
    const u64 PAi0  = pk(s0Ai, RJL ? s1Ai : s0Ai);
    const u64 PAiN0 = pk(-s0Ai, RJL ? -s1Ai : -s0Ai);
    const u64 PBr0  = pk(s0Br, RJL ? s1Br : s0Br);
    const u64 PBi0  = pk(s0Bi, RJL ? s1Bi : s0Bi);
    const u64 PBiN0 = pk(-s0Bi, RJL ? -s1Bi : -s0Bi);
    u64 PAr1 = PAr0, PAi1 = PAi0, PAiN1 = PAiN0;
    u64 PBr1 = PBr0, PBi1 = PBi0, PBiN1 = PBiN0;
    if (RJH != 0) {
        PAr1  = pk(s1Ar, RJL ? s0Ar : s1Ar);
        PAi1  = pk(s1Ai, RJL ? s0Ai : s1Ai);
        PAiN1 = pk(-s1Ai, RJL ? -s0Ai : -s1Ai);
        PBr1  = pk(s1Br, RJL ? s0Br : s1Br);
        PBi1  = pk(s1Bi, RJL ? s0Bi : s1Bi);
        PBiN1 = pk(-s1Bi, RJL ? -s0Bi : -s1Bi);
    }

#pragma unroll
    for (int g = 0; g < 16; g++) {
        // Orbit pick: process exactly one of {g, g^JH} — test the CANONICAL bit
        // only (multi-bit JH must not skip mixed-bit groups).
        if (JH != 0 && (g & JHB) != 0) continue;
        const int pg = g ^ JH;
        const u64 sr = Vr[g], si = Vi[g];
        u64 or_g, oi_g;
        u64 sr2 = 0, si2 = 0, or_p = 0, oi_p = 0;
        if (LM != 0) { or_g = shfl64(Vr[pg], LM); oi_g = shfl64(Vi[pg], LM); }
        else         { or_g = Vr[pg];             oi_g = Vi[pg]; }
        if (JH != 0) {
            sr2 = Vr[pg]; si2 = Vi[pg];
            if (LM != 0) { or_p = shfl64(Vr[g], LM); oi_p = shfl64(Vi[g], LM); }
            else         { or_p = sr;                oi_p = si; }
        }
        if (JL != 0) {
            or_g = swap2(or_g); oi_g = swap2(oi_g);
            if (JH != 0) { or_p = swap2(or_p); oi_p = swap2(oi_p); }
        }
        {
            const bool v = (__popc(g & RJH) & 1) != 0;
            const u64 pAr = v ? PAr1 : PAr0, pAi = v ? PAi1 : PAi0;
            const u64 pAiN = v ? PAiN1 : PAiN0;
            const u64 pBr = v ? PBr1 : PBr0, pBi = v ? PBi1 : PBi0;
            const u64 pBiN = v ? PBiN1 : PBiN0;
            Vr[g] = f2fma(pAr, sr, f2fma(pAiN, si, f2fma(pBr, or_g, f2mul(pBiN, oi_g))));
            Vi[g] = f2fma(pAr, si, f2fma(pAi,  sr, f2fma(pBr, oi_g, f2mul(pBi,  or_g))));
        }
        if (JH != 0) {
            const bool v = (__popc(pg & RJH) & 1) != 0;
            const u64 pAr = v ? PAr1 : PAr0, pAi = v ? PAi1 : PAi0;
            const u64 pAiN = v ? PAiN1 : PAiN0;
            const u64 pBr = v ? PBr1 : PBr0, pBi = v ? PBi1 : PBi0;
            const u64 pBiN = v ? PBiN1 : PBiN0;
            Vr[pg] = f2fma(pAr, sr2, f2fma(pAiN, si2, f2fma(pBr, or_p, f2mul(pBiN, oi_p))));
            Vi[pg] = f2fma(pAr, si2, f2fma(pAi,  sr2, f2fma(pBr, oi_p, f2mul(pBi,  or_p))));
        }
    }
}

__global__ void __launch_bounds__(256)
vqc_kernel(const float* __restrict__ x,
           const float* __restrict__ bias,
           const float* __restrict__ scale,
           float* __restrict__ out) {
    __shared__ float srot[NL * NQ * 8];
    for (int i = threadIdx.x; i < NL * NQ * 8; i += blockDim.x)
        srot[i] = g_rot[i];
    __syncthreads();

    const int lane = threadIdx.x & 31;
    const int b = (blockIdx.x * blockDim.x + threadIdx.x) >> 5;

    float xc = 0.0f, xs = 0.0f;
    if (lane < NQ) {
        float h = 0.5f * x[b * NQ + lane];
        sincosf(h, &xs, &xc);
    }

    // Packed state: group g holds amplitudes j=2g (lo), 2g+1 (hi); lane = bits[9:5]
    u64 Vr[16], Vi[16];
#pragma unroll
    for (int g = 0; g < 16; g++) { Vr[g] = 0; Vi[g] = 0; }
    Vr[0] = (lane == 0) ? 0x3F800000ull : 0ull;  // |0..0> : lo = 1.0f

    float M[8];

#define APPLY_GATE(L, Q)                                                        \
    do {                                                                        \
        float c_ = __shfl_sync(0xffffffffu, xc, Q);                             \
        float s_ = __shfl_sync(0xffffffffu, xs, Q);                             \
        build_fused(srot + ((L) * NQ + (Q)) * 8, c_, s_, M);                    \
        constexpr unsigned gm_ = gate_mask(L, Q);                               \
        constexpr unsigned gr_ = gate_role(L, Q);                               \
        gate_apply<(int)((gm_ >> 5) & 31u), (int)(gm_ & 31u),                   \
                   (int)((gr_ >> 5) & 31u), (int)(gr_ & 31u)>(Vr, Vi, lane, M); \
    } while (0)

#define APPLY_LAYER(L)                                                          \
    APPLY_GATE(L, 0); APPLY_GATE(L, 1); APPLY_GATE(L, 2); APPLY_GATE(L, 3);     \
    APPLY_GATE(L, 4); APPLY_GATE(L, 5); APPLY_GATE(L, 6); APPLY_GATE(L, 7);     \
    APPLY_GATE(L, 8); APPLY_GATE(L, 9);

    APPLY_LAYER(0)
    APPLY_LAYER(1)
    APPLY_LAYER(2)
    APPLY_LAYER(3)

#undef APPLY_LAYER
#undef APPLY_GATE

    // Probabilities (unpacked)
    float p[32];
#pragma unroll
    for (int g = 0; g < 16; g++) {
        u64 P = f2fma(Vr[g], Vr[g], f2mul(Vi[g], Vi[g]));
        upk(P, p[2 * g], p[2 * g + 1]);
    }

    // <Z> on physical wires 0..3 with tracked sign masks (rows of T^{-NL})
    float ev[NC];
#pragma unroll
    for (int c = 0; c < NC; c++) {
        constexpr unsigned rows[NC] = {meas_row(0), meas_row(1), meas_row(2), meas_row(3)};
        const unsigned row = rows[c];
        float S = 0.0f;
#pragma unroll
        for (int j = 0; j < 32; j++) {
            if (par10(j & (row & 31u))) S -= p[j]; else S += p[j];
        }
        const bool ls = (__popc(lane & (int)(row >> 5)) & 1) != 0;
        float v = ls ? -S : S;
        v += __shfl_xor_sync(0xffffffffu, v, 16);
        v += __shfl_xor_sync(0xffffffffu, v, 8);
        v += __shfl_xor_sync(0xffffffffu, v, 4);
        v += __shfl_xor_sync(0xffffffffu, v, 2);
        v += __shfl_xor_sync(0xffffffffu, v, 1);
        ev[c] = v;
    }

    if (lane == 0) {
        float t0 = (ev[0] + bias[0]) * scale[0];
        float t1 = (ev[1] + bias[1]) * scale[1];
        float t2 = (ev[2] + bias[2]) * scale[2];
        float t3 = (ev[3] + bias[3]) * scale[3];
        float m = fmaxf(fmaxf(t0, t1), fmaxf(t2, t3));
        float e0 = expf(t0 - m), e1 = expf(t1 - m), e2 = expf(t2 - m), e3 = expf(t3 - m);
        float inv = 1.0f / (e0 + e1 + e2 + e3);
        reinterpret_cast<float4*>(out)[b] =
            make_float4(e0 * inv, e1 * inv, e2 * inv, e3 * inv);
    }
}

extern "C" void kernel_launch(void* const* d_in, const int* in_sizes, int n_in,
                              void* d_out, int out_size) {
    const float* x       = (const float*)d_in[0];  // (B, NQ)
    const float* weights = (const float*)d_in[1];  // (NL, NQ, 3)
    const float* bias    = (const float*)d_in[2];  // (C,)
    const float* scale   = (const float*)d_in[3];  // (C,)
    float* out = (float*)d_out;                    // (B, C)

    rot_precompute_kernel<<<1, 64>>>(weights);
    vqc_kernel<<<BATCH / 8, 256>>>(x, bias, scale, out);
}

// round 4
// speedup vs baseline: 1.4617x; 1.0520x over previous
#include <cuda_runtime.h>

#define NQ 10
#define NL 4
#define NC 4
#define BATCH 2048

typedef unsigned long long u64;

// ============================================================================
// GF(2) linear-map tracking of the CNOT ring (all compile-time).
// Index bits: wire q <-> bit (9-q). Bits 5..9 = lane bits 0..4, bits 0..4 = local.
// Invariant: psi_phys[p] = sigma[F p], F = T^l at layer l.
// Gate on physical bit b: stored pair-XOR mask = column b of T^l,
//                         role(s) = <row_b(T^{-l}), s>.
// Measurement sign mask for bit b: row b of T^{-NL}.
// ============================================================================

struct G10 { unsigned r[10]; };

__host__ __device__ constexpr G10 gid10() {
    G10 c{};
    for (int i = 0; i < 10; i++) c.r[i] = 1u << i;
    return c;
}
__host__ __device__ constexpr G10 gmul(const G10 a, const G10 b) {
    G10 c{};
    for (int i = 0; i < 10; i++) {
        unsigned m = 0;
        for (int j = 0; j < 10; j++)
            if ((a.r[i] >> j) & 1u) m ^= b.r[j];
        c.r[i] = m;
    }
    return c;
}
__host__ __device__ constexpr G10 makeT() {
    G10 c{};
    for (int i = 0; i < 8; i++) c.r[i] = (1u << i) | (1u << (i + 1));
    c.r[8] = 0x301u;
    c.r[9] = 0x201u;
    return c;
}
__host__ __device__ constexpr G10 makeTinv() {
    G10 c{};
    for (int i = 0; i < 9; i++) c.r[i] = (0x3FFu >> i) << i;
    c.r[9] = 0x1FFu;
    return c;
}
__host__ __device__ constexpr G10 gpow(const G10 a, int k) {
    G10 c = gid10();
    for (int t = 0; t < k; t++) c = gmul(a, c);
    return c;
}
__host__ __device__ constexpr bool iseq(const G10 a, const G10 b) {
    for (int i = 0; i < 10; i++) if (a.r[i] != b.r[i]) return false;
    return true;
}
static_assert(iseq(gmul(makeT(), makeTinv()), gid10()), "Tinv wrong");

__host__ __device__ constexpr unsigned colmask(const G10 m, int b) {
    unsigned v = 0;
    for (int i = 0; i < 10; i++) v |= ((m.r[i] >> b) & 1u) << i;
    return v;
}
__host__ __device__ constexpr unsigned gate_mask(int l, int q) {
    return colmask(gpow(makeT(), l), 9 - q);
}
__host__ __device__ constexpr unsigned gate_role(int l, int q) {
    return gpow(makeTinv(), l).r[9 - q];
}
__host__ __device__ constexpr unsigned meas_row(int wire) {
    return gpow(makeTinv(), NL).r[9 - wire];
}
__host__ __device__ constexpr int par10(unsigned v) {
    int p = 0;
    for (int i = 0; i < 10; i++) p ^= (int)((v >> i) & 1u);
    return p;
}

// ============================================================================
// Packed f32x2 helpers (Blackwell FFMA2)
// ============================================================================
__device__ __forceinline__ u64 pk(float lo, float hi) {
    u64 d;
    asm("mov.b64 %0, {%1, %2};" : "=l"(d) : "f"(lo), "f"(hi));
    return d;
}
__device__ __forceinline__ void upk(u64 v, float& lo, float& hi) {
    asm("mov.b64 {%0, %1}, %2;" : "=f"(lo), "=f"(hi) : "l"(v));
}
__device__ __forceinline__ u64 f2fma(u64 a, u64 b, u64 c) {
    u64 d;
    asm("fma.rn.f32x2 %0, %1, %2, %3;" : "=l"(d) : "l"(a), "l"(b), "l"(c));
    return d;
}
__device__ __forceinline__ u64 f2mul(u64 a, u64 b) {
    u64 d;
    asm("mul.rn.f32x2 %0, %1, %2;" : "=l"(d) : "l"(a), "l"(b));
    return d;
}
__device__ __forceinline__ u64 swap2(u64 v) { return (v >> 32) | (v << 32); }
__device__ __forceinline__ u64 shfl64(u64 v, int m) {
    return __shfl_xor_sync(0xffffffffu, v, m);
}

// ============================================================================
// Rot matrix precompute: [NL][NQ][8]
// ============================================================================
__device__ float g_rot[NL * NQ * 8];

__global__ void rot_precompute_kernel(const float* __restrict__ w) {
    int i = threadIdx.x;
    if (i < NL * NQ) {
        float phi = w[i * 3 + 0], theta = w[i * 3 + 1], omega = w[i * 3 + 2];
        float st, ct;  sincosf(0.5f * theta, &st, &ct);
        float spo, cpo; sincosf(0.5f * (phi + omega), &spo, &cpo);
        float spm, cpm; sincosf(0.5f * (phi - omega), &spm, &cpm);
        float* m = g_rot + i * 8;
        m[0] =  cpo * ct;  m[1] = -spo * ct;
        m[2] = -cpm * st;  m[3] = -spm * st;
        m[4] =  cpm * st;  m[5] = -spm * st;
        m[6] =  cpo * ct;  m[7] =  spo * ct;
    }
}

// Fused gate M = Rot * RX;  RX = [[c, -i s], [-i s, c]]
__device__ __forceinline__ void build_fused(const float* __restrict__ rm,
                                            float c, float s, float* M) {
    float R00r = rm[0], R00i = rm[1], R01r = rm[2], R01i = rm[3];
    float R10r = rm[4], R10i = rm[5], R11r = rm[6], R11i = rm[7];
    M[0] =  c * R00r + s * R01i;   M[1] =  c * R00i - s * R01r;
    M[2] =  s * R00i + c * R01r;   M[3] = -s * R00r + c * R01i;
    M[4] =  c * R10r + s * R11i;   M[5] =  c * R10i - s * R11r;
    M[6] =  s * R10i + c * R11r;   M[7] = -s * R10r + c * R11i;
}

// ============================================================================
// Generalized 1q gate: pair-XOR mask (LM lane, JM local), role mask (RL, RJ).
// State packed: group g holds j=2g (lo), 2g+1 (hi).
// ============================================================================
template <int LM, int JM, int RL, int RJ>
__device__ __forceinline__ void gate_apply(u64* Vr, u64* Vi, int lane,
                                           const float* M) {
    constexpr int JH = JM >> 1, JL = JM & 1;
    constexpr int JHB = JH & (-JH);   // canonical (lowest) bit for orbit pick
    constexpr int RJH = RJ >> 1, RJL = RJ & 1;

    const bool rl = (RL != 0) && ((__popc(lane & RL) & 1) != 0);
    const float s0Ar = rl ? M[6] : M[0], s0Ai = rl ? M[7] : M[1];
    const float s0Br = rl ? M[4] : M[2], s0Bi = rl ? M[5] : M[3];
    const float s1Ar = rl ? M[0] : M[6], s1Ai = rl ? M[1] : M[7];
    const float s1Br = rl ? M[2] : M[4], s1Bi = rl ? M[3] : M[5];

    const u64 PAr0  = pk(s0Ar, RJL ? s1Ar : s0Ar);
    const u64 PAi0  = pk(s0Ai, RJL ? s1Ai : s0Ai);
    const u64 PAiN0 = pk(-s0Ai, RJL ? -s1Ai : -s0Ai);
    const u64 PBr0  = pk(s0Br, RJL ? s1Br : s0Br);
    const u64 PBi0  = pk(s0Bi, RJL ? s1Bi : s0Bi);
    const u64 PBiN0 = pk(-s0Bi, RJL ? -s1Bi : -s0Bi);
    u64 PAr1 = PAr0, PAi1 = PAi0, PAiN1 = PAiN0;
    u64 PBr1 = PBr0, PBi1 = PBi0, PBiN1 = PBiN0;
    if (RJH != 0) {
        PAr1  = pk(s1Ar, RJL ? s0Ar : s1Ar);
        PAi1  = pk(s1Ai, RJL ? s0Ai : s1Ai);
        PAiN1 = pk(-s1Ai, RJL ? -s0Ai : -s1Ai);
        PBr1  = pk(s1Br, RJL ? s0Br : s1Br);
        PBi1  = pk(s1Bi, RJL ? s0Bi : s1Bi);
        PBiN1 = pk(-s1Bi, RJL ? -s0Bi : -s1Bi);
    }

#pragma unroll
    for (int g = 0; g < 16; g++) {
        if (JH != 0 && (g & JHB) != 0) continue;  // one rep per {g, g^JH} orbit
        const int pg = g ^ JH;
        const u64 sr = Vr[g], si = Vi[g];
        u64 or_g, oi_g;
        u64 sr2 = 0, si2 = 0, or_p = 0, oi_p = 0;
        if (LM != 0) { or_g = shfl64(Vr[pg], LM); oi_g = shfl64(Vi[pg], LM); }
        else         { or_g = Vr[pg];             oi_g = Vi[pg]; }
        if (JH != 0) {
            sr2 = Vr[pg]; si2 = Vi[pg];
            if (LM != 0) { or_p = shfl64(Vr[g], LM); oi_p = shfl64(Vi[g], LM); }
            else         { or_p = sr;                oi_p = si; }
        }
        if (JL != 0) {
            or_g = swap2(or_g); oi_g = swap2(oi_g);
            if (JH != 0) { or_p = swap2(or_p); oi_p = swap2(oi_p); }
        }
        {
            const bool v = (__popc(g & RJH) & 1) != 0;
            const u64 pAr = v ? PAr1 : PAr0, pAi = v ? PAi1 : PAi0;
            const u64 pAiN = v ? PAiN1 : PAiN0;
            const u64 pBr = v ? PBr1 : PBr0, pBi = v ? PBi1 : PBi0;
            const u64 pBiN = v ? PBiN1 : PBiN0;
            Vr[g] = f2fma(pAr, sr, f2fma(pAiN, si, f2fma(pBr, or_g, f2mul(pBiN, oi_g))));
            Vi[g] = f2fma(pAr, si, f2fma(pAi,  sr, f2fma(pBr, oi_g, f2mul(pBi,  or_g))));
        }
        if (JH != 0) {
            const bool v = (__popc(pg & RJH) & 1) != 0;
            const u64 pAr = v ? PAr1 : PAr0, pAi = v ? PAi1 : PAi0;
            const u64 pAiN = v ? PAiN1 : PAiN0;
            const u64 pBr = v ? PBr1 : PBr0, pBi = v ? PBi1 : PBi0;
            const u64 pBiN = v ? PBiN1 : PBiN0;
            Vr[pg] = f2fma(pAr, sr2, f2fma(pAiN, si2, f2fma(pBr, or_p, f2mul(pBiN, oi_p))));
            Vi[pg] = f2fma(pAr, si2, f2fma(pAi,  sr2, f2fma(pBr, oi_p, f2mul(pBi,  or_p))));
        }
    }
}

__global__ void __launch_bounds__(256, 2)
vqc_kernel(const float* __restrict__ x,
           const float* __restrict__ bias,
           const float* __restrict__ scale,
           float* __restrict__ out) {
    __shared__ float srot[NL * NQ * 8];
    for (int i = threadIdx.x; i < NL * NQ * 8; i += blockDim.x)
        srot[i] = g_rot[i];
    __syncthreads();

    const int lane = threadIdx.x & 31;
    const int b = (blockIdx.x * blockDim.x + threadIdx.x) >> 5;

    float xc = 0.0f, xs = 0.0f;
    if (lane < NQ) {
        float h = 0.5f * x[b * NQ + lane];
        sincosf(h, &xs, &xc);
    }

    // Packed state: group g holds amplitudes j=2g (lo), 2g+1 (hi); lane = bits[9:5]
    u64 Vr[16], Vi[16];
#pragma unroll
    for (int g = 0; g < 16; g++) { Vr[g] = 0; Vi[g] = 0; }
    Vr[0] = (lane == 0) ? 0x3F800000ull : 0ull;  // |0..0>

    float M[8];

#define APPLY_GATE(L, Q)                                                        \
    do {                                                                        \
        float c_ = __shfl_sync(0xffffffffu, xc, Q);                             \
        float s_ = __shfl_sync(0xffffffffu, xs, Q);                             \
        build_fused(srot + ((L) * NQ + (Q)) * 8, c_, s_, M);                    \
        constexpr unsigned gm_ = gate_mask(L, Q);                               \
        constexpr unsigned gr_ = gate_role(L, Q);                               \
        gate_apply<(int)((gm_ >> 5) & 31u), (int)(gm_ & 31u),                   \
                   (int)((gr_ >> 5) & 31u), (int)(gr_ & 31u)>(Vr, Vi, lane, M); \
    } while (0)

#define APPLY_LAYER(L)                                                          \
    APPLY_GATE(L, 0); APPLY_GATE(L, 1); APPLY_GATE(L, 2); APPLY_GATE(L, 3);     \
    APPLY_GATE(L, 4); APPLY_GATE(L, 5); APPLY_GATE(L, 6); APPLY_GATE(L, 7);     \
    APPLY_GATE(L, 8); APPLY_GATE(L, 9);

    APPLY_LAYER(0)
    APPLY_LAYER(1)
    APPLY_LAYER(2)
    APPLY_LAYER(3)

#undef APPLY_LAYER
#undef APPLY_GATE

    // Single-pass measurement: 4 signed sums over probabilities.
    // Sign for class c at local index j: par10(j & row_lo). Lane part applied after.
    constexpr unsigned rows0 = meas_row(0), rows1 = meas_row(1);
    constexpr unsigned rows2 = meas_row(2), rows3 = meas_row(3);
    float S0 = 0.f, S1 = 0.f, S2 = 0.f, S3 = 0.f;
#pragma unroll
    for (int g = 0; g < 16; g++) {
        u64 P = f2fma(Vr[g], Vr[g], f2mul(Vi[g], Vi[g]));
        float plo, phi_;
        upk(P, plo, phi_);
#pragma unroll
        for (int h = 0; h < 2; h++) {
            const int j = 2 * g + h;
            const float pv = h ? phi_ : plo;
            S0 += par10(j & (rows0 & 31u)) ? -pv : pv;
            S1 += par10(j & (rows1 & 31u)) ? -pv : pv;
            S2 += par10(j & (rows2 & 31u)) ? -pv : pv;
            S3 += par10(j & (rows3 & 31u)) ? -pv : pv;
        }
    }
    float ev[NC];
    {
        const unsigned lrow[NC] = {rows0 >> 5, rows1 >> 5, rows2 >> 5, rows3 >> 5};
        float Ss[NC] = {S0, S1, S2, S3};
#pragma unroll
        for (int c = 0; c < NC; c++) {
            const bool ls = (__popc(lane & (int)lrow[c]) & 1) != 0;
            float v = ls ? -Ss[c] : Ss[c];
            v += __shfl_xor_sync(0xffffffffu, v, 16);
            v += __shfl_xor_sync(0xffffffffu, v, 8);
            v += __shfl_xor_sync(0xffffffffu, v, 4);
            v += __shfl_xor_sync(0xffffffffu, v, 2);
            v += __shfl_xor_sync(0xffffffffu, v, 1);
            ev[c] = v;
        }
    }

    if (lane == 0) {
        float t0 = (ev[0] + bias[0]) * scale[0];
        float t1 = (ev[1] + bias[1]) * scale[1];
        float t2 = (ev[2] + bias[2]) * scale[2];
        float t3 = (ev[3] + bias[3]) * scale[3];
        float m = fmaxf(fmaxf(t0, t1), fmaxf(t2, t3));
        float e0 = expf(t0 - m), e1 = expf(t1 - m), e2 = expf(t2 - m), e3 = expf(t3 - m);
        float inv = 1.0f / (e0 + e1 + e2 + e3);
        reinterpret_cast<float4*>(out)[b] =
            make_float4(e0 * inv, e1 * inv, e2 * inv, e3 * inv);
    }
}

extern "C" void kernel_launch(void* const* d_in, const int* in_sizes, int n_in,
                              void* d_out, int out_size) {
    const float* x       = (const float*)d_in[0];  // (B, NQ)
    const float* weights = (const float*)d_in[1];  // (NL, NQ, 3)
    const float* bias    = (const float*)d_in[2];  // (C,)
    const float* scale   = (const float*)d_in[3];  // (C,)
    float* out = (float*)d_out;                    // (B, C)

    rot_precompute_kernel<<<1, 64>>>(weights);
    vqc_kernel<<<BATCH / 8, 256>>>(x, bias, scale, out);
}

// round 5
// speedup vs baseline: 1.5523x; 1.0620x over previous
#include <cuda_runtime.h>

#define NQ 10
#define NL 4
#define NC 4
#define BATCH 2048

typedef unsigned long long u64;

// ============================================================================
// GF(2) linear-map tracking of the CNOT ring (all compile-time).
// Index bits: wire q <-> bit (9-q). Bits 5..9 = lane bits 0..4, bits 0..4 = local.
// Invariant: psi_phys[p] = sigma[F p], F = T^l at layer l.
// Gate on physical bit b: stored pair-XOR mask = column b of T^l,
//                         role(s) = <row_b(T^{-l}), s>.
// Measurement sign mask for bit b: row b of T^{-NL}.
// ============================================================================

struct G10 { unsigned r[10]; };

__host__ __device__ constexpr G10 gid10() {
    G10 c{};
    for (int i = 0; i < 10; i++) c.r[i] = 1u << i;
    return c;
}
__host__ __device__ constexpr G10 gmul(const G10 a, const G10 b) {
    G10 c{};
    for (int i = 0; i < 10; i++) {
        unsigned m = 0;
        for (int j = 0; j < 10; j++)
            if ((a.r[i] >> j) & 1u) m ^= b.r[j];
        c.r[i] = m;
    }
    return c;
}
__host__ __device__ constexpr G10 makeT() {
    G10 c{};
    for (int i = 0; i < 8; i++) c.r[i] = (1u << i) | (1u << (i + 1));
    c.r[8] = 0x301u;
    c.r[9] = 0x201u;
    return c;
}
__host__ __device__ constexpr G10 makeTinv() {
    G10 c{};
    for (int i = 0; i < 9; i++) c.r[i] = (0x3FFu >> i) << i;
    c.r[9] = 0x1FFu;
    return c;
}
__host__ __device__ constexpr G10 gpow(const G10 a, int k) {
    G10 c = gid10();
    for (int t = 0; t < k; t++) c = gmul(a, c);
    return c;
}
__host__ __device__ constexpr bool iseq(const G10 a, const G10 b) {
    for (int i = 0; i < 10; i++) if (a.r[i] != b.r[i]) return false;
    return true;
}
static_assert(iseq(gmul(makeT(), makeTinv()), gid10()), "Tinv wrong");

__host__ __device__ constexpr unsigned colmask(const G10 m, int b) {
    unsigned v = 0;
    for (int i = 0; i < 10; i++) v |= ((m.r[i] >> b) & 1u) << i;
    return v;
}
__host__ __device__ constexpr unsigned gate_mask(int l, int q) {
    return colmask(gpow(makeT(), l), 9 - q);
}
__host__ __device__ constexpr unsigned gate_role(int l, int q) {
    return gpow(makeTinv(), l).r[9 - q];
}
__host__ __device__ constexpr unsigned meas_row(int wire) {
    return gpow(makeTinv(), NL).r[9 - wire];
}
__host__ __device__ constexpr int par10(unsigned v) {
    int p = 0;
    for (int i = 0; i < 10; i++) p ^= (int)((v >> i) & 1u);
    return p;
}

// ============================================================================
// Packed f32x2 helpers (Blackwell FFMA2)
// ============================================================================
__device__ __forceinline__ u64 pk(float lo, float hi) {
    u64 d;
    asm("mov.b64 %0, {%1, %2};" : "=l"(d) : "f"(lo), "f"(hi));
    return d;
}
__device__ __forceinline__ void upk(u64 v, float& lo, float& hi) {
    asm("mov.b64 {%0, %1}, %2;" : "=f"(lo), "=f"(hi) : "l"(v));
}
__device__ __forceinline__ u64 f2fma(u64 a, u64 b, u64 c) {
    u64 d;
    asm("fma.rn.f32x2 %0, %1, %2, %3;" : "=l"(d) : "l"(a), "l"(b), "l"(c));
    return d;
}
__device__ __forceinline__ u64 f2fma_neg(u64 a, u64 b, u64 c) {
    // c - a*b  (via neg on a is not available; do mul then sub)
    u64 m, d;
    asm("mul.rn.f32x2 %0, %1, %2;" : "=l"(m) : "l"(a), "l"(b));
    asm("sub.rn.f32x2 %0, %1, %2;" : "=l"(d) : "l"(c), "l"(m));
    return d;
}
__device__ __forceinline__ u64 f2mul(u64 a, u64 b) {
    u64 d;
    asm("mul.rn.f32x2 %0, %1, %2;" : "=l"(d) : "l"(a), "l"(b));
    return d;
}
__device__ __forceinline__ u64 swap2(u64 v) { return (v >> 32) | (v << 32); }
__device__ __forceinline__ u64 shfl64(u64 v, int m) {
    return __shfl_xor_sync(0xffffffffu, v, m);
}

// ============================================================================
// Rot matrix precompute: [NL][NQ][8]
// ============================================================================
__device__ float g_rot[NL * NQ * 8];

__global__ void rot_precompute_kernel(const float* __restrict__ w) {
    int i = threadIdx.x;
    if (i < NL * NQ) {
        float phi = w[i * 3 + 0], theta = w[i * 3 + 1], omega = w[i * 3 + 2];
        float st, ct;  sincosf(0.5f * theta, &st, &ct);
        float spo, cpo; sincosf(0.5f * (phi + omega), &spo, &cpo);
        float spm, cpm; sincosf(0.5f * (phi - omega), &spm, &cpm);
        float* m = g_rot + i * 8;
        m[0] =  cpo * ct;  m[1] = -spo * ct;
        m[2] = -cpm * st;  m[3] = -spm * st;
        m[4] =  cpm * st;  m[5] = -spm * st;
        m[6] =  cpo * ct;  m[7] =  spo * ct;
    }
}

// Fused gate M = Rot * RX;  RX = [[c, -i s], [-i s, c]]
__device__ __forceinline__ void build_fused(const float* __restrict__ rm,
                                            float c, float s, float* M) {
    float R00r = rm[0], R00i = rm[1], R01r = rm[2], R01i = rm[3];
    float R10r = rm[4], R10i = rm[5], R11r = rm[6], R11i = rm[7];
    M[0] =  c * R00r + s * R01i;   M[1] =  c * R00i - s * R01r;
    M[2] =  s * R00i + c * R01r;   M[3] = -s * R00r + c * R01i;
    M[4] =  c * R10r + s * R11i;   M[5] =  c * R10i - s * R11r;
    M[6] =  s * R10i + c * R11r;   M[7] = -s * R10r + c * R11i;
}

// Column 0 only of the fused gate (acting on |0>): a = M00, b = M10.
__device__ __forceinline__ void fused_col0(const float* __restrict__ rm,
                                           float c, float s,
                                           float& ar_, float& ai_,
                                           float& br_, float& bi_) {
    ar_ = c * rm[0] + s * rm[3];
    ai_ = c * rm[1] - s * rm[2];
    br_ = c * rm[4] + s * rm[7];
    bi_ = c * rm[5] - s * rm[6];
}

// ============================================================================
// Generalized 1q gate: pair-XOR mask (LM lane, JM local), role mask (RL, RJ).
// State packed: group g holds j=2g (lo), 2g+1 (hi).
// ============================================================================
template <int LM, int JM, int RL, int RJ>
__device__ __forceinline__ void gate_apply(u64* Vr, u64* Vi, int lane,
                                           const float* M) {
    constexpr int JH = JM >> 1, JL = JM & 1;
    constexpr int JHB = JH & (-JH);   // canonical (lowest) bit for orbit pick
    constexpr int RJH = RJ >> 1, RJL = RJ & 1;

    const bool rl = (RL != 0) && ((__popc(lane & RL) & 1) != 0);
    const float s0Ar = rl ? M[6] : M[0], s0Ai = rl ? M[7] : M[1];
    const float s0Br = rl ? M[4] : M[2], s0Bi = rl ? M[5] : M[3];
    const float s1Ar = rl ? M[0] : M[6], s1Ai = rl ? M[1] : M[7];
    const float s1Br = rl ? M[2] : M[4], s1Bi = rl ? M[3] : M[5];

    const u64 PAr0  = pk(s0Ar, RJL ? s1Ar : s0Ar);
    const u64 PAi0  = pk(s0Ai, RJL ? s1Ai : s0Ai);
    const u64 PAiN0 = pk(-s0Ai, RJL ? -s1Ai : -s0Ai);
    const u64 PBr0  = pk(s0Br, RJL ? s1Br : s0Br);
    const u64 PBi0  = pk(s0Bi, RJL ? s1Bi : s0Bi);
    const u64 PBiN0 = pk(-s0Bi, RJL ? -s1Bi : -s0Bi);
    u64 PAr1 = PAr0, PAi1 = PAi0, PAiN1 = PAiN0;
    u64 PBr1 = PBr0, PBi1 = PBi0, PBiN1 = PBiN0;
    if (RJH != 0) {
        PAr1  = pk(s1Ar, RJL ? s0Ar : s1Ar);
        PAi1  = pk(s1Ai, RJL ? s0Ai : s1Ai);
        PAiN1 = pk(-s1Ai, RJL ? -s0Ai : -s1Ai);
        PBr1  = pk(s1Br, RJL ? s0Br : s1Br);
        PBi1  = pk(s1Bi, RJL ? s0Bi : s1Bi);
        PBiN1 = pk(-s1Bi, RJL ? -s0Bi : -s1Bi);
    }

#pragma unroll
    for (int g = 0; g < 16; g++) {
        if (JH != 0 && (g & JHB) != 0) continue;  // one rep per {g, g^JH} orbit
        const int pg = g ^ JH;
        const u64 sr = Vr[g], si = Vi[g];
        u64 or_g, oi_g;
        u64 sr2 = 0, si2 = 0, or_p = 0, oi_p = 0;
        if (LM != 0) { or_g = shfl64(Vr[pg], LM); oi_g = shfl64(Vi[pg], LM); }
        else         { or_g = Vr[pg];             oi_g = Vi[pg]; }
        if (JH != 0) {
            sr2 = Vr[pg]; si2 = Vi[pg];
            if (LM != 0) { or_p = shfl64(Vr[g], LM); oi_p = shfl64(Vi[g], LM); }
            else         { or_p = sr;                oi_p = si; }
        }
        if (JL != 0) {
            or_g = swap2(or_g); oi_g = swap2(oi_g);
            if (JH != 0) { or_p = swap2(or_p); oi_p = swap2(oi_p); }
        }
        {
            const bool v = (__popc(g & RJH) & 1) != 0;
            const u64 pAr = v ? PAr1 : PAr0, pAi = v ? PAi1 : PAi0;
            const u64 pAiN = v ? PAiN1 : PAiN0;
            const u64 pBr = v ? PBr1 : PBr0, pBi = v ? PBi1 : PBi0;
            const u64 pBiN = v ? PBiN1 : PBiN0;
            Vr[g] = f2fma(pAr, sr, f2fma(pAiN, si, f2fma(pBr, or_g, f2mul(pBiN, oi_g))));
            Vi[g] = f2fma(pAr, si, f2fma(pAi,  sr, f2fma(pBr, oi_g, f2mul(pBi,  or_g))));
        }
        if (JH != 0) {
            const bool v = (__popc(pg & RJH) & 1) != 0;
            const u64 pAr = v ? PAr1 : PAr0, pAi = v ? PAi1 : PAi0;
            const u64 pAiN = v ? PAiN1 : PAiN0;
            const u64 pBr = v ? PBr1 : PBr0, pBi = v ? PBi1 : PBi0;
            const u64 pBiN = v ? PBiN1 : PBiN0;
            Vr[pg] = f2fma(pAr, sr2, f2fma(pAiN, si2, f2fma(pBr, or_p, f2mul(pBiN, oi_p))));
            Vi[pg] = f2fma(pAr, si2, f2fma(pAi,  sr2, f2fma(pBr, oi_p, f2mul(pBi,  or_p))));
        }
    }
}

__global__ void __launch_bounds__(256, 2)
vqc_kernel(const float* __restrict__ x,
           const float* __restrict__ bias,
           const float* __restrict__ scale,
           float* __restrict__ out) {
    __shared__ float srot[NL * NQ * 8];
    for (int i = threadIdx.x; i < NL * NQ * 8; i += blockDim.x)
        srot[i] = g_rot[i];
    __syncthreads();

    const int lane = threadIdx.x & 31;
    const int b = (blockIdx.x * blockDim.x + threadIdx.x) >> 5;

    float xc = 0.0f, xs = 0.0f;
    if (lane < NQ) {
        float h = 0.5f * x[b * NQ + lane];
        sincosf(h, &xs, &xc);
    }

    // ========================================================================
    // Layer 0 via product-state construction (state after layer-0 1q gates
    // is exactly the tensor product of per-wire columns (a_q, b_q); the
    // layer-0 CNOT ring is absorbed by the GF(2) tracking: masks at l=1
    // already account for it).
    // ========================================================================
    u64 Vr[16], Vi[16];

    // Lane factor: wires 0..4 <-> lane bits 4..0 (wire q -> lane bit 4-q)
    float Lfr = 1.0f, Lfi = 0.0f;
#pragma unroll
    for (int q = 0; q < 5; q++) {
        float c_ = __shfl_sync(0xffffffffu, xc, q);
        float s_ = __shfl_sync(0xffffffffu, xs, q);
        float ar_, ai_, br_, bi_;
        fused_col0(srot + q * 8, c_, s_, ar_, ai_, br_, bi_);
        const bool bit = ((lane >> (4 - q)) & 1) != 0;
        const float fr = bit ? br_ : ar_;
        const float fi = bit ? bi_ : ai_;
        const float nr = Lfr * fr - Lfi * fi;
        const float ni = Lfr * fi + Lfi * fr;
        Lfr = nr; Lfi = ni;
    }

    // Local wires 5..9 <-> local bits 4..0 (wire q -> local bit 9-q)
    float lar[5], lai[5], lbr[5], lbi[5];  // index m = local bit, wire = 9-m
#pragma unroll
    for (int m = 0; m < 5; m++) {
        const int q = 9 - m;
        float c_ = __shfl_sync(0xffffffffu, xc, q);
        float s_ = __shfl_sync(0xffffffffu, xs, q);
        fused_col0(srot + q * 8, c_, s_, lar[m], lai[m], lbr[m], lbi[m]);
    }

    // Group 0 = (j=0: Lf*a_w9, j=1: Lf*b_w9) packed  (local bit 0 = wire 9)
    {
        const float e0r = Lfr * lar[0] - Lfi * lai[0];
        const float e0i = Lfr * lai[0] + Lfi * lar[0];
        const float e1r = Lfr * lbr[0] - Lfi * lbi[0];
        const float e1i = Lfr * lbi[0] + Lfi * lbr[0];
        Vr[0] = pk(e0r, e1r);
        Vi[0] = pk(e0i, e1i);
    }
    // Doubling over local bits 1..4 (group bit m-1), wire 9-m
#pragma unroll
    for (int m = 1; m < 5; m++) {
        const u64 Ar2 = pk(lar[m], lar[m]), Ai2 = pk(lai[m], lai[m]);
        const u64 Br2 = pk(lbr[m], lbr[m]), Bi2 = pk(lbi[m], lbi[m]);
        const int half = 1 << (m - 1);
#pragma unroll
        for (int g = 0; g < 16; g++) {
            if (g >= half) continue;
            const u64 r = Vr[g], i = Vi[g];
            Vr[g | half] = f2fma_neg(i, Bi2, f2mul(r, Br2));
            Vi[g | half] = f2fma(r, Bi2, f2mul(i, Br2));
            Vr[g]        = f2fma_neg(i, Ai2, f2mul(r, Ar2));
            Vi[g]        = f2fma(r, Ai2, f2mul(i, Ar2));
        }
    }

    float M[8];

#define APPLY_GATE(L, Q)                                                        \
    do {                                                                        \
        float c_ = __shfl_sync(0xffffffffu, xc, Q);                             \
        float s_ = __shfl_sync(0xffffffffu, xs, Q);                             \
        build_fused(srot + ((L) * NQ + (Q)) * 8, c_, s_, M);                    \
        constexpr unsigned gm_ = gate_mask(L, Q);                               \
        constexpr unsigned gr_ = gate_role(L, Q);                               \
        gate_apply<(int)((gm_ >> 5) & 31u), (int)(gm_ & 31u),                   \
                   (int)((gr_ >> 5) & 31u), (int)(gr_ & 31u)>(Vr, Vi, lane, M); \
    } while (0)

#define APPLY_LAYER(L)                                                          \
    APPLY_GATE(L, 0); APPLY_GATE(L, 1); APPLY_GATE(L, 2); APPLY_GATE(L, 3);     \
    APPLY_GATE(L, 4); APPLY_GATE(L, 5); APPLY_GATE(L, 6); APPLY_GATE(L, 7);     \
    APPLY_GATE(L, 8); APPLY_GATE(L, 9);

    APPLY_LAYER(1)
    APPLY_LAYER(2)
    APPLY_LAYER(3)

#undef APPLY_LAYER
#undef APPLY_GATE

    // Single-pass measurement: 4 signed sums over probabilities.
    constexpr unsigned rows0 = meas_row(0), rows1 = meas_row(1);
    constexpr unsigned rows2 = meas_row(2), rows3 = meas_row(3);
    float S0 = 0.f, S1 = 0.f, S2 = 0.f, S3 = 0.f;
#pragma unroll
    for (int g = 0; g < 16; g++) {
        u64 P = f2fma(Vr[g], Vr[g], f2mul(Vi[g], Vi[g]));
        float plo, phi_;
        upk(P, plo, phi_);
#pragma unroll
        for (int h = 0; h < 2; h++) {
            const int j = 2 * g + h;
            const float pv = h ? phi_ : plo;
            S0 += par10(j & (rows0 & 31u)) ? -pv : pv;
            S1 += par10(j & (rows1 & 31u)) ? -pv : pv;
            S2 += par10(j & (rows2 & 31u)) ? -pv : pv;
            S3 += par10(j & (rows3 & 31u)) ? -pv : pv;
        }
    }
    float ev[NC];
    {
        const unsigned lrow[NC] = {rows0 >> 5, rows1 >> 5, rows2 >> 5, rows3 >> 5};
        float Ss[NC] = {S0, S1, S2, S3};
#pragma unroll
        for (int c = 0; c < NC; c++) {
            const bool ls = (__popc(lane & (int)lrow[c]) & 1) != 0;
            float v = ls ? -Ss[c] : Ss[c];
            v += __shfl_xor_sync(0xffffffffu, v, 16);
            v += __shfl_xor_sync(0xffffffffu, v, 8);
            v += __shfl_xor_sync(0xffffffffu, v, 4);
            v += __shfl_xor_sync(0xffffffffu, v, 2);
            v += __shfl_xor_sync(0xffffffffu, v, 1);
            ev[c] = v;
        }
    }

    if (lane == 0) {
        float t0 = (ev[0] + bias[0]) * scale[0];
        float t1 = (ev[1] + bias[1]) * scale[1];
        float t2 = (ev[2] + bias[2]) * scale[2];
        float t3 = (ev[3] + bias[3]) * scale[3];
        float m = fmaxf(fmaxf(t0, t1), fmaxf(t2, t3));
        float e0 = expf(t0 - m), e1 = expf(t1 - m), e2 = expf(t2 - m), e3 = expf(t3 - m);
        float inv = 1.0f / (e0 + e1 + e2 + e3);
        reinterpret_cast<float4*>(out)[b] =
            make_float4(e0 * inv, e1 * inv, e2 * inv, e3 * inv);
    }
}

extern "C" void kernel_launch(void* const* d_in, const int* in_sizes, int n_in,
                              void* d_out, int out_size) {
    const float* x       = (const float*)d_in[0];  // (B, NQ)
    const float* weights = (const float*)d_in[1];  // (NL, NQ, 3)
    const float* bias    = (const float*)d_in[2];  // (C,)
    const float* scale   = (const float*)d_in[3];  // (C,)
    float* out = (float*)d_out;                    // (B, C)

    rot_precompute_kernel<<<1, 64>>>(weights);
    vqc_kernel<<<BATCH / 8, 256>>>(x, bias, scale, out);
}